// round 7
// baseline (speedup 1.0000x reference)
#include <cuda_runtime.h>
#include <math.h>
#include <stdint.h>

#define NB 64
#define CC 256
#define TT 64
#define VV 25
#define HID 16
#define NCV (NB*CC)            // 16384 (n,c) chunks
#define CHUNK (TT*VV)          // 1600 floats per (n,c)

#define GRID 512
#define THREADS 256
#define CPC 32                 // chunks per CTA (GRID*CPC = NCV); 32 | 256 -> single n per CTA

__device__ float g_avg[NCV];
__device__ float g_mx[NCV];
__device__ unsigned g_bar;     // monotonic epoch barrier counter (zero-init, replay-safe)

__constant__ int c_perm[VV] = {0,1,2,3,20,  8,9,10,11,23,24,  16,17,18,19,  4,5,6,7,21,22,  12,13,14,15};
__constant__ int c_grp[VV]  = {0,0,0,0,0,   1,1,1,1,1,1,      2,2,2,2,      3,3,3,3,3,3,    4,4,4,4};

__global__ __launch_bounds__(THREADS, 6)
void fused_kernel(const float* __restrict__ x,
                  const float* __restrict__ W1, const float* __restrict__ b1,
                  const float* __restrict__ W2, const float* __restrict__ b2,
                  float* __restrict__ out) {
    __shared__ float sx[2 * CHUNK];     // 12.8 KB staging (2 chunks)
    __shared__ float ps[8], pm[8];
    __shared__ float pavg[CPC], pmx[CPC];
    __shared__ float spa[CC], spm[CC];
    __shared__ float parts[160];        // [0:80) avg-branch dot, [80:160) mx-branch dot
    __shared__ float hid[80];
    __shared__ float g5[160];           // gate per (f, cl)
    __shared__ float sgate[CPC * 32];   // gate per (cl, joint)
    __shared__ int   lut[64];           // [0:25) perm, [32:57) grp

    const int tid  = threadIdx.x;
    const int base = blockIdx.x * CPC;          // first chunk
    const int n    = base >> 8;
    const int c0   = base & (CC - 1);
    if (tid < VV) { lut[tid] = c_perm[tid]; lut[32 + tid] = c_grp[tid]; }

    // ================= Phase A: coalesced read of own chunks + torso reduce =================
    // (float4 staging requests every sector -> fills L2 completely for phase C)
#pragma unroll 1
    for (int s = 0; s < CPC / 2; s++) {
        const float4* __restrict__ src =
            reinterpret_cast<const float4*>(x + ((size_t)base + 2 * s) * CHUNK);
        for (int idx = tid; idx < 2 * CHUNK / 4; idx += THREADS)
            reinterpret_cast<float4*>(sx)[idx] = src[idx];
        __syncthreads();

        const int cl = tid >> 7, r = tid & 127;
        float sum = 0.f, mx = -INFINITY;
        if (r < TT) {
            const float* row = sx + cl * CHUNK + r * VV;
            float v0 = row[0], v1 = row[1], v2 = row[2], v3 = row[3], v4 = row[20];
            sum = (v0 + v1) + (v2 + v3) + v4;
            mx  = fmaxf(fmaxf(v0, v1), fmaxf(fmaxf(v2, v3), v4));
        }
#pragma unroll
        for (int o = 16; o; o >>= 1) {
            sum += __shfl_xor_sync(0xffffffffu, sum, o);
            mx   = fmaxf(mx, __shfl_xor_sync(0xffffffffu, mx, o));
        }
        const int wid = tid >> 5, lane = tid & 31;
        if (lane == 0) { ps[wid] = sum; pm[wid] = mx; }
        __syncthreads();
        if (tid < 2) {
            pavg[2 * s + tid] = ps[tid * 4] + ps[tid * 4 + 1];
            pmx [2 * s + tid] = fmaxf(pm[tid * 4], pm[tid * 4 + 1]);
        }
        __syncthreads();
    }
    if (tid < CPC) {
        g_avg[base + tid] = pavg[tid] * (1.0f / 320.0f);
        g_mx [base + tid] = pmx[tid];
    }

    // ================= Grid barrier (epoch-based, replay-safe) =================
    __threadfence();
    __syncthreads();
    if (tid == 0) {
        unsigned old = atomicAdd(&g_bar, 1u);
        unsigned target = old - (old % GRID) + GRID;   // end of this launch's epoch
        while (atomicAdd(&g_bar, 0u) < target) __nanosleep(64);
        __threadfence();
    }
    __syncthreads();

    // ================= Phase B: gates for this CTA's 32 channels =================
    spa[tid] = g_avg[n * CC + tid];
    spm[tid] = g_mx [n * CC + tid];
    __syncthreads();
    if (tid < 160) {                       // one (branch, f*16+h) dot per thread
        const int which = tid >= 80;
        const int i = tid - which * 80;    // f*16 + h
        const float* w1row = W1 + i * CC;
        const float* p = which ? spm : spa;
        float s = 0.f;
#pragma unroll 8
        for (int c = 0; c < CC; c++) s = fmaf(w1row[c], p[c], s);
        parts[tid] = s;
    }
    __syncthreads();
    if (tid < 80) {
        float b = b1[tid];
        hid[tid] = fmaxf(parts[tid] + b, 0.f) + fmaxf(parts[80 + tid] + b, 0.f);
    }
    __syncthreads();
    if (tid < 160) {                       // f = tid>>5, cl = tid&31
        const int f = tid >> 5, cl = tid & 31, c = c0 + cl;
        const float* w2row = W2 + ((size_t)f * CC + c) * HID;
        float o = 2.0f * b2[f * CC + c];
#pragma unroll
        for (int h = 0; h < HID; h++) o = fmaf(hid[f * HID + h], w2row[h], o);
        g5[f * 32 + cl] = 1.0f / (1.0f + expf(-o));
    }
    __syncthreads();
    for (int q = tid; q < CPC * 32; q += THREADS) {   // sgate[cl*32+j]
        const int j = q & 31;
        if (j < VV) sgate[q] = g5[lut[32 + j] * 32 + (q >> 5)];
    }
    __syncthreads();

    // ================= Phase C: reread own chunks (L2-hot), permute+gate, stream out ========
#pragma unroll 1
    for (int s = 0; s < CPC / 2; s++) {
        const size_t off = ((size_t)base + 2 * s) * CHUNK;
        const float4* __restrict__ src = reinterpret_cast<const float4*>(x + off);
        float4* __restrict__ dst = reinterpret_cast<float4*>(out + off);
        for (int idx = tid; idx < 2 * CHUNK / 4; idx += THREADS)
            reinterpret_cast<float4*>(sx)[idx] = src[idx];
        __syncthreads();
        for (int idx = tid; idx < 2 * CHUNK / 4; idx += THREADS) {
            int e0 = idx * 4;
            int cl2 = e0 / CHUNK;
            int rem = e0 - cl2 * CHUNK;
            float r[4];
#pragma unroll
            for (int k = 0; k < 4; k++) {
                int e = rem + k;
                int t = e / VV;
                int j = e - t * VV;
                r[k] = sx[cl2 * CHUNK + t * VV + lut[j]] * sgate[(2 * s + cl2) * 32 + j];
            }
            __stcs(&dst[idx], make_float4(r[0], r[1], r[2], r[3]));
        }
        __syncthreads();
    }
}

extern "C" void kernel_launch(void* const* d_in, const int* in_sizes, int n_in,
                              void* d_out, int out_size) {
    const float* x  = (const float*)d_in[0];
    const float* W1 = (const float*)d_in[1];
    const float* b1 = (const float*)d_in[2];
    const float* W2 = (const float*)d_in[3];
    const float* b2 = (const float*)d_in[4];
    float* out = (float*)d_out;

    fused_kernel<<<GRID, THREADS>>>(x, W1, b1, W2, b2, out);
}

// round 8
// speedup vs baseline: 3.2252x; 3.2252x over previous
#include <cuda_runtime.h>
#include <math.h>

#define NB 64
#define CC 256
#define TT 64
#define VV 25
#define HID 16
#define NCV (NB*CC)            // 16384 (n,c) chunks
#define CHUNK (TT*VV)          // 1600 floats per (n,c)
#define F4PC (CHUNK/4)         // 400 float4 per chunk

#define CPB 2                  // chunks per block in scale kernel
#define SCALE_THREADS 256

// scratch (allocation-free rule: __device__ globals)
__device__ float g_avg[NCV];
__device__ float g_mx[NCV];
__device__ float g_gates[NB * 5 * CC];

// output joint -> input joint (TORSO, LEFT_HAND, LEFT_LEG, RIGHT_HAND, RIGHT_LEG)
__constant__ int c_perm[VV] = {0,1,2,3,20,  8,9,10,11,23,24,  16,17,18,19,  4,5,6,7,21,22,  12,13,14,15};
__constant__ int c_grp[VV]  = {0,0,0,0,0,   1,1,1,1,1,1,      2,2,2,2,      3,3,3,3,3,3,    4,4,4,4};

// ---------------- K1: torso mean/max per (n,c) — register-only, fully coalesced ----------------
// One warp per chunk. Each lane streams float4s and predicated-accumulates torso elements
// (j = e mod 25; torso iff j<4 or j==20). No SMEM, no block barriers -> deep load batching.
__global__ __launch_bounds__(256) void reduce_kernel(const float* __restrict__ x) {
    const int gw   = (blockIdx.x * blockDim.x + threadIdx.x) >> 5;   // chunk id
    const int lane = threadIdx.x & 31;
    const float4* __restrict__ src = reinterpret_cast<const float4*>(x + (size_t)gw * CHUNK);

    float s = 0.f, m = -INFINITY;
#pragma unroll
    for (int i = 0; i < 13; i++) {
        const int q = lane + 32 * i;                 // float4 index within chunk
        if (q < F4PC) {
            const float4 v = src[q];
            const int e0 = q * 4;
            int j = e0 - (e0 / VV) * VV;             // e0 % 25
            float vv[4] = {v.x, v.y, v.z, v.w};
#pragma unroll
            for (int k = 0; k < 4; k++) {
                const bool torso = (j < 4) | (j == 20);
                s = torso ? (s + vv[k]) : s;
                m = torso ? fmaxf(m, vv[k]) : m;
                j++; if (j == VV) j = 0;
            }
        }
    }
#pragma unroll
    for (int o = 16; o; o >>= 1) {
        s += __shfl_xor_sync(0xffffffffu, s, o);
        m = fmaxf(m, __shfl_xor_sync(0xffffffffu, m, o));
    }
    if (lane == 0) {
        g_avg[gw] = s * (1.0f / 320.0f);
        g_mx[gw]  = m;
    }
}

// ---------------- K2: per-(n,group) MLP -> gates ----------------
__global__ void mlp_kernel(const float* __restrict__ W1, const float* __restrict__ b1,
                           const float* __restrict__ W2, const float* __restrict__ b2) {
    int blk = blockIdx.x;          // n*5 + f
    int n = blk / 5, f = blk % 5;
    __shared__ float pa[CC], pm[CC], hs[HID];
    int tid = threadIdx.x;
    pa[tid] = g_avg[n * CC + tid];
    pm[tid] = g_mx[n * CC + tid];
    __syncthreads();

    int w = tid >> 5, lane = tid & 31;   // 8 warps, 2 hidden units each
#pragma unroll
    for (int hh = 0; hh < 2; hh++) {
        int h = w * 2 + hh;
        const float* w1row = W1 + (f * HID + h) * CC;
        float sa = 0.f, sm = 0.f;
#pragma unroll
        for (int c = lane; c < CC; c += 32) {
            float wv = w1row[c];
            sa = fmaf(wv, pa[c], sa);
            sm = fmaf(wv, pm[c], sm);
        }
#pragma unroll
        for (int o = 16; o; o >>= 1) {
            sa += __shfl_xor_sync(0xffffffffu, sa, o);
            sm += __shfl_xor_sync(0xffffffffu, sm, o);
        }
        if (lane == 0) {
            float b = b1[f * HID + h];
            hs[h] = fmaxf(sa + b, 0.f) + fmaxf(sm + b, 0.f);
        }
    }
    __syncthreads();

    const float* w2row = W2 + ((size_t)f * CC + tid) * HID;
    float o = 2.0f * b2[f * CC + tid];
#pragma unroll
    for (int h = 0; h < HID; h++) o = fmaf(hs[h], w2row[h], o);
    g_gates[n * (5 * CC) + f * CC + tid] = 1.0f / (1.0f + expf(-o));
}

// ---------------- K3: out[n,c,t,j] = x[n,c,t,perm[j]] * gate[n,grp[j],c] ----------------
// LIFO chunk order vs reduce's stream (L2 reuse); __ldcs reads (x is dead after this,
// evict-first misses don't evict resident x); __stcs streaming writes.
__global__ __launch_bounds__(SCALE_THREADS) void scale_kernel(const float* __restrict__ x,
                                                              float* __restrict__ out) {
    __shared__ float sx[CPB * CHUNK];   // 12.8 KB
    __shared__ float sgate[CPB * 32];
    __shared__ int   sperm[32];
    const int tid = threadIdx.x;
    const int base = (gridDim.x - 1 - blockIdx.x) * CPB;   // LIFO vs reduce's stream order
    const float4* __restrict__ src = reinterpret_cast<const float4*>(x + (size_t)base * CHUNK);
    float4* __restrict__ dst = reinterpret_cast<float4*>(out + (size_t)base * CHUNK);

    if (tid < VV) sperm[tid] = c_perm[tid];
    if (tid >= 32 && tid < 32 + CPB * VV) {
        int q = tid - 32, cl = q / VV, j = q - cl * VV;
        int nc = base + cl;
        sgate[cl * 32 + j] = g_gates[(nc >> 8) * (5 * CC) + c_grp[j] * CC + (nc & (CC - 1))];
    }

#pragma unroll
    for (int idx = tid; idx < CPB * CHUNK / 4; idx += SCALE_THREADS) {
        reinterpret_cast<float4*>(sx)[idx] = __ldcs(&src[idx]);
    }
    __syncthreads();

#pragma unroll
    for (int idx = tid; idx < CPB * CHUNK / 4; idx += SCALE_THREADS) {
        int e0 = idx * 4;
        int cl = e0 / CHUNK;
        int rem = e0 - cl * CHUNK;
        float r[4];
#pragma unroll
        for (int k = 0; k < 4; k++) {
            int e = rem + k;
            int t = e / VV;
            int j = e - t * VV;
            r[k] = sx[cl * CHUNK + t * VV + sperm[j]] * sgate[cl * 32 + j];
        }
        __stcs(&dst[idx], make_float4(r[0], r[1], r[2], r[3]));
    }
}

extern "C" void kernel_launch(void* const* d_in, const int* in_sizes, int n_in,
                              void* d_out, int out_size) {
    const float* x  = (const float*)d_in[0];
    const float* W1 = (const float*)d_in[1];
    const float* b1 = (const float*)d_in[2];
    const float* W2 = (const float*)d_in[3];
    const float* b2 = (const float*)d_in[4];
    float* out = (float*)d_out;

    reduce_kernel<<<NCV / 8, 256>>>(x);                 // 16384 warps, register-only
    mlp_kernel<<<NB * 5, 256>>>(W1, b1, W2, b2);        // 320 blocks
    scale_kernel<<<NCV / CPB, SCALE_THREADS>>>(x, out); // 8192 blocks, LIFO
}

// round 9
// speedup vs baseline: 3.3265x; 1.0314x over previous
#include <cuda_runtime.h>
#include <math.h>

#define NB 64
#define CC 256
#define TT 64
#define VV 25
#define HID 16
#define NCV (NB*CC)            // 16384 (n,c) chunks
#define CHUNK (TT*VV)          // 1600 floats per (n,c)

#define CPB 2                  // chunks per block (scale + reduce)
#define SCALE_THREADS 256

// scratch (allocation-free rule: __device__ globals)
__device__ float g_avg[NCV];
__device__ float g_mx[NCV];
__device__ float g_gates[NB * 5 * CC];

// output joint -> input joint (TORSO, LEFT_HAND, LEFT_LEG, RIGHT_HAND, RIGHT_LEG)
__constant__ int c_perm[VV] = {0,1,2,3,20,  8,9,10,11,23,24,  16,17,18,19,  4,5,6,7,21,22,  12,13,14,15};
__constant__ int c_grp[VV]  = {0,0,0,0,0,   1,1,1,1,1,1,      2,2,2,2,      3,3,3,3,3,3,    4,4,4,4};

// ---------------- K1: torso mean/max per (n,c), coalesced via SMEM staging ----------------
// Streams all of x through L2 (x = 105 MB < 126 MB L2 -> fully resident at kernel end).
__global__ __launch_bounds__(256) void reduce_kernel(const float* __restrict__ x) {
    __shared__ float sx[CPB * CHUNK];      // 12.8 KB
    __shared__ float ps[8], pm[8];
    const int tid = threadIdx.x;
    const int base = blockIdx.x * CPB;
    const float4* __restrict__ src = reinterpret_cast<const float4*>(x + (size_t)base * CHUNK);

#pragma unroll
    for (int idx = tid; idx < CPB * CHUNK / 4; idx += 256)
        reinterpret_cast<float4*>(sx)[idx] = src[idx];
    __syncthreads();

    const int cl = tid >> 7;               // chunk-local 0..1
    const int r  = tid & 127;
    float s = 0.f, m = -INFINITY;
    if (r < TT) {                          // one t-row per active thread
        const float* row = sx + cl * CHUNK + r * VV;   // stride 25: conflict-free banks
        float v0 = row[0], v1 = row[1], v2 = row[2], v3 = row[3], v4 = row[20];
        s = (v0 + v1) + (v2 + v3) + v4;
        m = fmaxf(fmaxf(v0, v1), fmaxf(fmaxf(v2, v3), v4));
    }
#pragma unroll
    for (int o = 16; o; o >>= 1) {
        s += __shfl_xor_sync(0xffffffffu, s, o);
        m = fmaxf(m, __shfl_xor_sync(0xffffffffu, m, o));
    }
    const int wid = tid >> 5, lane = tid & 31;
    if (lane == 0) { ps[wid] = s; pm[wid] = m; }
    __syncthreads();
    if (tid < CPB) {
        float ss = ps[tid * 4] + ps[tid * 4 + 1];
        float mm = fmaxf(pm[tid * 4], pm[tid * 4 + 1]);
        g_avg[base + tid] = ss * (1.0f / 320.0f);
        g_mx[base + tid]  = mm;
    }
}

// ---------------- K2: per-(n,group) MLP -> gates ----------------
__global__ void mlp_kernel(const float* __restrict__ W1, const float* __restrict__ b1,
                           const float* __restrict__ W2, const float* __restrict__ b2) {
    int blk = blockIdx.x;          // n*5 + f
    int n = blk / 5, f = blk % 5;
    __shared__ float pa[CC], pm[CC], hs[HID];
    int tid = threadIdx.x;
    pa[tid] = g_avg[n * CC + tid];
    pm[tid] = g_mx[n * CC + tid];
    __syncthreads();

    int w = tid >> 5, lane = tid & 31;   // 8 warps, 2 hidden units each
#pragma unroll
    for (int hh = 0; hh < 2; hh++) {
        int h = w * 2 + hh;
        const float* w1row = W1 + (f * HID + h) * CC;
        float sa = 0.f, sm = 0.f;
#pragma unroll
        for (int c = lane; c < CC; c += 32) {
            float wv = w1row[c];
            sa = fmaf(wv, pa[c], sa);
            sm = fmaf(wv, pm[c], sm);
        }
#pragma unroll
        for (int o = 16; o; o >>= 1) {
            sa += __shfl_xor_sync(0xffffffffu, sa, o);
            sm += __shfl_xor_sync(0xffffffffu, sm, o);
        }
        if (lane == 0) {
            float b = b1[f * HID + h];
            hs[h] = fmaxf(sa + b, 0.f) + fmaxf(sm + b, 0.f);
        }
    }
    __syncthreads();

    const float* w2row = W2 + ((size_t)f * CC + tid) * HID;
    float o = 2.0f * b2[f * CC + tid];
#pragma unroll
    for (int h = 0; h < HID; h++) o = fmaf(hs[h], w2row[h], o);
    g_gates[n * (5 * CC) + f * CC + tid] = 1.0f / (1.0f + expf(-o));
}

// ---------------- K3: out[n,c,t,j] = x[n,c,t,perm[j]] * gate[n,grp[j],c] ----------------
// LIFO chunk order (consume most-recently-cached x first). Stores are WRITE-THROUGH
// (__stwt): no L2 allocation for the output stream, so it cannot evict resident x.
__global__ __launch_bounds__(SCALE_THREADS) void scale_kernel(const float* __restrict__ x,
                                                              float* __restrict__ out) {
    __shared__ float sx[CPB * CHUNK];   // 12.8 KB
    __shared__ float sgate[CPB * 32];
    __shared__ int   sperm[32];
    const int tid = threadIdx.x;
    const int base = (gridDim.x - 1 - blockIdx.x) * CPB;   // LIFO vs reduce's stream order
    const float4* __restrict__ src = reinterpret_cast<const float4*>(x + (size_t)base * CHUNK);
    float4* __restrict__ dst = reinterpret_cast<float4*>(out + (size_t)base * CHUNK);

    if (tid < VV) sperm[tid] = c_perm[tid];
    if (tid >= 32 && tid < 32 + CPB * VV) {
        int q = tid - 32, cl = q / VV, j = q - cl * VV;
        int nc = base + cl;
        sgate[cl * 32 + j] = g_gates[(nc >> 8) * (5 * CC) + c_grp[j] * CC + (nc & (CC - 1))];
    }

#pragma unroll
    for (int idx = tid; idx < CPB * CHUNK / 4; idx += SCALE_THREADS) {
        reinterpret_cast<float4*>(sx)[idx] = src[idx];
    }
    __syncthreads();

#pragma unroll
    for (int idx = tid; idx < CPB * CHUNK / 4; idx += SCALE_THREADS) {
        int e0 = idx * 4;
        int cl = e0 / CHUNK;
        int rem = e0 - cl * CHUNK;
        float r[4];
#pragma unroll
        for (int k = 0; k < 4; k++) {
            int e = rem + k;
            int t = e / VV;
            int j = e - t * VV;
            r[k] = sx[cl * CHUNK + t * VV + sperm[j]] * sgate[cl * 32 + j];
        }
        __stwt(&dst[idx], make_float4(r[0], r[1], r[2], r[3]));
    }
}

extern "C" void kernel_launch(void* const* d_in, const int* in_sizes, int n_in,
                              void* d_out, int out_size) {
    const float* x  = (const float*)d_in[0];
    const float* W1 = (const float*)d_in[1];
    const float* b1 = (const float*)d_in[2];
    const float* W2 = (const float*)d_in[3];
    const float* b2 = (const float*)d_in[4];
    float* out = (float*)d_out;

    reduce_kernel<<<NCV / CPB, 256>>>(x);               // 8192 blocks, streams x into L2
    mlp_kernel<<<NB * 5, 256>>>(W1, b1, W2, b2);        // 320 blocks
    scale_kernel<<<NCV / CPB, SCALE_THREADS>>>(x, out); // 8192 blocks, LIFO + __stwt
}